// round 1
// baseline (speedup 1.0000x reference)
#include <cuda_runtime.h>
#include <cuda_bf16.h>

// ---------------------------------------------------------------------------
// SCN: per rank r with L (N x N), x (N x 64), W (2 x 64 x 64):
//   dinv_i = rsqrt(sum_j |L_ij|)  (0 if sum==0)
//   for layer in 0..1:  x = relu( dinv_i * sum_j L_ij * dinv_j * (x @ W[layer])_j )
//   pooled[b] = sum_{i: bel_i==b} x_i          (B=64)
//   out += pooled @ Wr + br                    (OUT=32)
// ---------------------------------------------------------------------------

#define NMAX   8192
#define CCH    64
#define BSEG   64
#define OUTC   32
#define SPLIT_ELEMS (131072 * 64)   // max S*N*64 scratch (S*N == 131072 always)

__device__ float g_dinv[3 * NMAX];
__device__ float g_u[3][NMAX * CCH];
__device__ float g_x[3][NMAX * CCH];
__device__ float g_part[SPLIT_ELEMS];
__device__ float g_pp[3 * 32 * BSEG * CCH];   // pooling partials (max 32 blocks/rank)
__device__ float g_pool[3 * BSEG * CCH];

// ---------------- rowsum -> dinv ----------------
__global__ void scn_rowsum(const float* __restrict__ L, float* __restrict__ dinv, int N) {
    int row = blockIdx.x;
    const float4* Lr = (const float4*)(L + (long)row * N);
    int n4 = N >> 2;
    float s = 0.f;
    for (int j = threadIdx.x; j < n4; j += blockDim.x) {
        float4 v = Lr[j];
        s += fabsf(v.x) + fabsf(v.y) + fabsf(v.z) + fabsf(v.w);
    }
#pragma unroll
    for (int o = 16; o > 0; o >>= 1) s += __shfl_down_sync(0xffffffffu, s, o);
    __shared__ float red[8];
    int lane = threadIdx.x & 31, w = threadIdx.x >> 5;
    if (lane == 0) red[w] = s;
    __syncthreads();
    if (threadIdx.x < 8) {
        s = red[threadIdx.x];
#pragma unroll
        for (int o = 4; o > 0; o >>= 1) s += __shfl_down_sync(0xffu, s, o);
        if (threadIdx.x == 0) dinv[row] = (s > 0.f) ? rsqrtf(s) : 0.f;
    }
}

// ---------------- u = dinv .* (x @ W)  (N x 64) ----------------
__global__ void scn_xw(const float* __restrict__ X, const float* __restrict__ W,
                       const float* __restrict__ dinv, float* __restrict__ U, int N) {
    __shared__ float Ws[64][64];
    __shared__ float Xs[32][64];
    int t = threadIdx.x;
    int r0 = blockIdx.x * 32;
#pragma unroll
    for (int j = 0; j < 4; j++)
        ((float4*)Ws)[t + 256 * j] = ((const float4*)W)[t + 256 * j];
#pragma unroll
    for (int j = 0; j < 2; j++)
        ((float4*)Xs)[t + 256 * j] = ((const float4*)(X + (long)r0 * 64))[t + 256 * j];
    __syncthreads();
    int c = t & 63, g = t >> 6;
    float acc[8] = {0.f, 0.f, 0.f, 0.f, 0.f, 0.f, 0.f, 0.f};
#pragma unroll 16
    for (int k = 0; k < 64; k++) {
        float w = Ws[k][c];
#pragma unroll
        for (int r = 0; r < 8; r++)
            acc[r] = fmaf(Xs[g * 8 + r][k], w, acc[r]);
    }
#pragma unroll
    for (int r = 0; r < 8; r++) {
        int row = r0 + g * 8 + r;
        U[(long)row * 64 + c] = dinv[row] * acc[r];
    }
}

// ---------------- split-K GEMM partial: P[s] += L[m, kchunk] @ U[kchunk, 64] ----
__global__ __launch_bounds__(64, 8)
void scn_gemm_partial(const float* __restrict__ L, const float* __restrict__ U,
                      float* __restrict__ P, int N, int kChunk) {
    __shared__ __align__(16) float Ls[64][33];
    __shared__ __align__(16) float Us[32][68];
    int t = threadIdx.x;
    int tm = t >> 3, tn = t & 7;
    int m0 = blockIdx.x * 64;
    long kbase = (long)blockIdx.y * kChunk;

    float acc[8][8];
#pragma unroll
    for (int i = 0; i < 8; i++)
#pragma unroll
        for (int j = 0; j < 8; j++) acc[i][j] = 0.f;

    int lr = t >> 3;   // 0..7  (L row group)
    int lc = t & 7;    // 0..7  (L float4 col)
    int ur = t >> 4;   // 0..3  (U row group)
    int uc = t & 15;   // 0..15 (U float4 col)

    for (int kt = 0; kt < kChunk; kt += 32) {
        long k0 = kbase + kt;
        // L tile 64x32 (row-major in smem, pad 33)
#pragma unroll
        for (int it = 0; it < 8; it++) {
            int row = lr + it * 8;
            float4 v = *(const float4*)(L + (long)(m0 + row) * N + k0 + lc * 4);
            Ls[row][lc * 4 + 0] = v.x; Ls[row][lc * 4 + 1] = v.y;
            Ls[row][lc * 4 + 2] = v.z; Ls[row][lc * 4 + 3] = v.w;
        }
        // U tile 32x64 (k-major, pad 68, float4 stores)
#pragma unroll
        for (int it = 0; it < 8; it++) {
            int row = ur + it * 4;
            float4 v = *(const float4*)(U + (k0 + row) * 64 + uc * 4);
            *(float4*)&Us[row][uc * 4] = v;
        }
        __syncthreads();
#pragma unroll 8
        for (int k = 0; k < 32; k++) {
            float a[8], b[8];
#pragma unroll
            for (int i = 0; i < 8; i++) a[i] = Ls[tm * 8 + i][k];
            float4 b0 = *(const float4*)&Us[k][tn * 4];
            float4 b1 = *(const float4*)&Us[k][32 + tn * 4];
            b[0] = b0.x; b[1] = b0.y; b[2] = b0.z; b[3] = b0.w;
            b[4] = b1.x; b[5] = b1.y; b[6] = b1.z; b[7] = b1.w;
#pragma unroll
            for (int i = 0; i < 8; i++)
#pragma unroll
                for (int j = 0; j < 8; j++)
                    acc[i][j] = fmaf(a[i], b[j], acc[i][j]);
        }
        __syncthreads();
    }
    float* Pb = P + (long)blockIdx.y * N * 64;
#pragma unroll
    for (int i = 0; i < 8; i++) {
        long m = m0 + tm * 8 + i;
        float4 v0 = make_float4(acc[i][0], acc[i][1], acc[i][2], acc[i][3]);
        float4 v1 = make_float4(acc[i][4], acc[i][5], acc[i][6], acc[i][7]);
        *(float4*)(Pb + m * 64 + tn * 4) = v0;
        *(float4*)(Pb + m * 64 + 32 + tn * 4) = v1;
    }
}

// ---------------- combine split-K partials, scale by dinv_i, relu ----------
__global__ void scn_combine_relu(const float4* __restrict__ P, const float* __restrict__ dinv,
                                 float4* __restrict__ X, int N, int S) {
    int idx = blockIdx.x * 256 + threadIdx.x;   // over N*16 float4
    int total4 = N * 16;
    if (idx >= total4) return;
    float4 s = P[idx];
    for (int q = 1; q < S; q++) {
        float4 v = P[(long)q * total4 + idx];
        s.x += v.x; s.y += v.y; s.z += v.z; s.w += v.w;
    }
    float d = dinv[idx >> 4];
    X[idx] = make_float4(fmaxf(d * s.x, 0.f), fmaxf(d * s.y, 0.f),
                         fmaxf(d * s.z, 0.f), fmaxf(d * s.w, 0.f));
}

// ---------------- deterministic segment pooling: partials per block -------
__global__ void scn_pool_partial(const float* __restrict__ X, const int* __restrict__ bel,
                                 float* __restrict__ PP, int N) {
    __shared__ float part[2][BSEG][CCH];   // 32 KB
    int t = threadIdx.x;                   // 128 threads
    int c = t & 63, s = t >> 6;
    for (int i = t; i < 2 * BSEG * CCH; i += 128) ((float*)part)[i] = 0.f;
    __syncthreads();
    int r0 = blockIdx.x * 256 + s * 128;
    for (int r = 0; r < 128; r++) {          // fixed sequential order -> deterministic
        int row = r0 + r;
        int b = bel[row];
        part[s][b][c] += X[(long)row * 64 + c];
    }
    __syncthreads();
    float* out = PP + (long)blockIdx.x * BSEG * CCH;
    for (int i = t; i < BSEG * CCH; i += 128)
        out[i] = ((float*)part)[i] + ((float*)part)[BSEG * CCH + i];
}

__global__ void scn_pool_reduce(const float* __restrict__ PP, float* __restrict__ pooled, int G) {
    int idx = blockIdx.x * 256 + threadIdx.x;   // 4096 total
    float s = 0.f;
    for (int g = 0; g < G; g++) s += PP[(long)g * BSEG * CCH + idx];
    pooled[idx] = s;
}

// ---------------- readout: out[b][o] = sum_r pooled_r[b] @ Wr_r + br_r ----
__global__ void scn_readout(const float* __restrict__ pool,     // [3][64*64]
                            const float* __restrict__ Wr0, const float* __restrict__ br0,
                            const float* __restrict__ Wr1, const float* __restrict__ br1,
                            const float* __restrict__ Wr2, const float* __restrict__ br2,
                            float* __restrict__ out) {
    int idx = blockIdx.x * 256 + threadIdx.x;
    if (idx >= BSEG * OUTC) return;
    int b = idx >> 5, o = idx & 31;
    float s = br0[o] + br1[o] + br2[o];
    const float* p0 = pool + 0 * BSEG * CCH + b * 64;
    const float* p1 = pool + 1 * BSEG * CCH + b * 64;
    const float* p2 = pool + 2 * BSEG * CCH + b * 64;
#pragma unroll 8
    for (int c = 0; c < 64; c++) {
        s = fmaf(p0[c], Wr0[c * 32 + o], s);
        s = fmaf(p1[c], Wr1[c * 32 + o], s);
        s = fmaf(p2[c], Wr2[c * 32 + o], s);
    }
    out[idx] = s;
}

// ---------------------------------------------------------------------------
static void* symAddr(const void* sym) {
    void* p = nullptr;
    cudaGetSymbolAddress(&p, sym);
    return p;
}

extern "C" void kernel_launch(void* const* d_in, const int* in_sizes, int n_in,
                              void* d_out, int out_size) {
    const float *x[3], *L[3], *W[3], *Wr[3], *br[3];
    const int* bel[3];

    // Detect input ordering from sizes:
    //  dict order:  x0,x1,x2,L0,L1,L2,bel0,bel1,bel2,W0,W1,W2,Wr0,br0,Wr1,br1,Wr2,br2
    //  sig  order:  x0,x1,x2,L0,L1,L2,W0,W1,W2,Wr0,br0,Wr1,br1,Wr2,br2,bel0,bel1,bel2
    //  alpha order: L0,L1,L2,W0,W1,W2,Wr0,Wr1,Wr2,bel0,bel1,bel2,br0,br1,br2,x0,x1,x2
    if (in_sizes[0] == 16777216) {                       // alpha
        for (int r = 0; r < 3; r++) {
            L[r]  = (const float*)d_in[0 + r];
            W[r]  = (const float*)d_in[3 + r];
            Wr[r] = (const float*)d_in[6 + r];
            bel[r]= (const int*)  d_in[9 + r];
            br[r] = (const float*)d_in[12 + r];
            x[r]  = (const float*)d_in[15 + r];
        }
    } else if (in_sizes[9] == 8192) {                    // dict
        for (int r = 0; r < 3; r++) {
            x[r]  = (const float*)d_in[0 + r];
            L[r]  = (const float*)d_in[3 + r];
            bel[r]= (const int*)  d_in[6 + r];
            W[r]  = (const float*)d_in[9 + r];
        }
        Wr[0] = (const float*)d_in[12]; br[0] = (const float*)d_in[13];
        Wr[1] = (const float*)d_in[14]; br[1] = (const float*)d_in[15];
        Wr[2] = (const float*)d_in[16]; br[2] = (const float*)d_in[17];
    } else {                                             // signature
        for (int r = 0; r < 3; r++) {
            x[r]  = (const float*)d_in[0 + r];
            L[r]  = (const float*)d_in[3 + r];
            W[r]  = (const float*)d_in[6 + r];
            bel[r]= (const int*)  d_in[15 + r];
        }
        Wr[0] = (const float*)d_in[9];  br[0] = (const float*)d_in[10];
        Wr[1] = (const float*)d_in[11]; br[1] = (const float*)d_in[12];
        Wr[2] = (const float*)d_in[13]; br[2] = (const float*)d_in[14];
    }

    int Ns[3];
    // x arrays are first 3 (dict/sig) or last 3 (alpha) — derive N from whichever slot holds x
    for (int r = 0; r < 3; r++) {
        // find via x pointer's size: recompute from in_sizes mapping above
        Ns[r] = 0;
    }
    if (in_sizes[0] == 16777216) {
        Ns[0] = in_sizes[15] / 64; Ns[1] = in_sizes[16] / 64; Ns[2] = in_sizes[17] / 64;
    } else {
        Ns[0] = in_sizes[0] / 64;  Ns[1] = in_sizes[1] / 64;  Ns[2] = in_sizes[2] / 64;
    }

    float* dinvAll = (float*)symAddr(g_dinv);
    float* uAll    = (float*)symAddr(g_u);
    float* xAll    = (float*)symAddr(g_x);
    float* part    = (float*)symAddr(g_part);
    float* pp      = (float*)symAddr(g_pp);
    float* pool    = (float*)symAddr(g_pool);
    float* out     = (float*)d_out;

    // 1) rowsums -> dinv
    for (int r = 0; r < 3; r++)
        scn_rowsum<<<Ns[r], 256>>>(L[r], dinvAll + r * NMAX, Ns[r]);

    // 2) two conv layers per rank
    for (int r = 0; r < 3; r++) {
        int N = Ns[r];
        int S = 131072 / N;            // 16 for N=8192, 32 for N=4096
        int kChunk = N / S;            // 512 / 128  (multiple of 32)
        float* dinv = dinvAll + r * NMAX;
        float* u    = uAll + (long)r * NMAX * CCH;
        float* xr   = xAll + (long)r * NMAX * CCH;
        const float* xin = x[r];
        for (int layer = 0; layer < 2; layer++) {
            scn_xw<<<N / 32, 256>>>(xin, W[r] + layer * 64 * 64, dinv, u, N);
            scn_gemm_partial<<<dim3(N / 64, S), 64>>>(L[r], u, part, N, kChunk);
            scn_combine_relu<<<N / 16, 256>>>((const float4*)part, dinv, (float4*)xr, N, S);
            xin = xr;
        }
    }

    // 3) deterministic pooling + readout
    for (int r = 0; r < 3; r++) {
        int N = Ns[r];
        int G = N / 256;
        float* xr  = xAll + (long)r * NMAX * CCH;
        float* ppr = pp + (long)r * 32 * BSEG * CCH;
        scn_pool_partial<<<G, 128>>>(xr, bel[r], ppr, N);
        scn_pool_reduce<<<16, 256>>>(ppr, pool + r * BSEG * CCH, G);
    }
    scn_readout<<<8, 256>>>(pool, Wr[0], br[0], Wr[1], br[1], Wr[2], br[2], out);
}

// round 2
// speedup vs baseline: 1.6180x; 1.6180x over previous
#include <cuda_runtime.h>
#include <cuda_bf16.h>

// ---------------------------------------------------------------------------
// SCN: per rank r with L (N x N), x (N x 64), W (2 x 64 x 64):
//   dinv_i = rsqrt(sum_j |L_ij|)  (0 if sum==0)
//   layer:  x = relu( dinv_i * sum_j L_ij * (dinv_j * (x @ W[layer])_j) )
//   pooled[b] = sum_{i: bel_i==b} x_i   (B=64);  out += pooled @ Wr + br
// GEMM (L @ U) now runs on tensor cores via mma.sync tf32.
// ---------------------------------------------------------------------------

#define NMAX   8192
#define CCH    64
#define BSEG   64
#define OUTC   32
#define SPLIT_ELEMS (2097152)          // S*N*64 scratch: 4*8192*64 = 8*4096*64

__device__ float g_dinv[3 * NMAX];
__device__ float g_u[3][NMAX * CCH];
__device__ float g_x[3][NMAX * CCH];
__device__ float g_part[SPLIT_ELEMS];
__device__ float g_pp[3 * 32 * BSEG * CCH];
__device__ float g_pool[3 * BSEG * CCH];

// ---------------- rowsum -> dinv ----------------
__global__ void scn_rowsum(const float* __restrict__ L, float* __restrict__ dinv, int N) {
    int row = blockIdx.x;
    const float4* Lr = (const float4*)(L + (long)row * N);
    int n4 = N >> 2;
    float s = 0.f;
    for (int j = threadIdx.x; j < n4; j += blockDim.x) {
        float4 v = Lr[j];
        s += fabsf(v.x) + fabsf(v.y) + fabsf(v.z) + fabsf(v.w);
    }
#pragma unroll
    for (int o = 16; o > 0; o >>= 1) s += __shfl_down_sync(0xffffffffu, s, o);
    __shared__ float red[8];
    int lane = threadIdx.x & 31, w = threadIdx.x >> 5;
    if (lane == 0) red[w] = s;
    __syncthreads();
    if (threadIdx.x < 8) {
        s = red[threadIdx.x];
#pragma unroll
        for (int o = 4; o > 0; o >>= 1) s += __shfl_down_sync(0xffu, s, o);
        if (threadIdx.x == 0) dinv[row] = (s > 0.f) ? rsqrtf(s) : 0.f;
    }
}

// ---------------- u = dinv .* (x @ W)  (N x 64) ----------------
__global__ void scn_xw(const float* __restrict__ X, const float* __restrict__ W,
                       const float* __restrict__ dinv, float* __restrict__ U, int N) {
    __shared__ float Ws[64][64];
    __shared__ float Xs[32][64];
    int t = threadIdx.x;
    int r0 = blockIdx.x * 32;
#pragma unroll
    for (int j = 0; j < 4; j++)
        ((float4*)Ws)[t + 256 * j] = ((const float4*)W)[t + 256 * j];
#pragma unroll
    for (int j = 0; j < 2; j++)
        ((float4*)Xs)[t + 256 * j] = ((const float4*)(X + (long)r0 * 64))[t + 256 * j];
    __syncthreads();
    int c = t & 63, g = t >> 6;
    float acc[8] = {0.f, 0.f, 0.f, 0.f, 0.f, 0.f, 0.f, 0.f};
#pragma unroll 16
    for (int k = 0; k < 64; k++) {
        float w = Ws[k][c];
#pragma unroll
        for (int r = 0; r < 8; r++)
            acc[r] = fmaf(Xs[g * 8 + r][k], w, acc[r]);
    }
#pragma unroll
    for (int r = 0; r < 8; r++) {
        int row = r0 + g * 8 + r;
        U[(long)row * 64 + c] = dinv[row] * acc[r];
    }
}

// ---------------- tf32 tensor-core split-K GEMM: P[s] = L[128-tile, kchunk] @ U ----
__device__ __forceinline__ unsigned f2tf32(float x) {
    unsigned r;
    asm("cvt.rna.tf32.f32 %0, %1;" : "=r"(r) : "f"(x));
    return r;
}

__global__ __launch_bounds__(256, 2)
void scn_gemm_tf32(const float* __restrict__ L, const float* __restrict__ U,
                   float* __restrict__ P, int N, int kChunk) {
    __shared__ __align__(16) unsigned Ls[128][36];   // [m][k], pad 36
    __shared__ __align__(16) unsigned Us[32][68];    // [k][n], pad 68
    int t = threadIdx.x;
    int wid = t >> 5, lane = t & 31;
    int g = lane >> 2, tq = lane & 3;
    int warp_m = wid & 3, warp_n = wid >> 2;          // 4 x 2 warp grid
    int m0 = blockIdx.x * 128;
    long kbase = (long)blockIdx.y * kChunk;
    int iters = kChunk / 32;

    float4 lbuf[4], ubuf[2];
    // prefetch tile 0
    {
        long k0 = kbase;
#pragma unroll
        for (int j = 0; j < 4; j++) {
            int f = t + 256 * j; int row = f >> 3, c4 = f & 7;
            lbuf[j] = *(const float4*)(L + (long)(m0 + row) * N + k0 + c4 * 4);
        }
#pragma unroll
        for (int j = 0; j < 2; j++) {
            int f = t + 256 * j; int row = f >> 4, c4 = f & 15;
            ubuf[j] = *(const float4*)(U + (k0 + row) * 64 + c4 * 4);
        }
    }

    float acc[2][4][4];
#pragma unroll
    for (int mi = 0; mi < 2; mi++)
#pragma unroll
        for (int ni = 0; ni < 4; ni++)
#pragma unroll
            for (int q = 0; q < 4; q++) acc[mi][ni][q] = 0.f;

    for (int it = 0; it < iters; it++) {
        // store current tile (convert to tf32 once here)
#pragma unroll
        for (int j = 0; j < 4; j++) {
            int f = t + 256 * j; int row = f >> 3, c4 = f & 7;
            uint4 v = make_uint4(f2tf32(lbuf[j].x), f2tf32(lbuf[j].y),
                                 f2tf32(lbuf[j].z), f2tf32(lbuf[j].w));
            *(uint4*)&Ls[row][c4 * 4] = v;
        }
#pragma unroll
        for (int j = 0; j < 2; j++) {
            int f = t + 256 * j; int row = f >> 4, c4 = f & 15;
            uint4 v = make_uint4(f2tf32(ubuf[j].x), f2tf32(ubuf[j].y),
                                 f2tf32(ubuf[j].z), f2tf32(ubuf[j].w));
            *(uint4*)&Us[row][c4 * 4] = v;
        }
        __syncthreads();
        if (it + 1 < iters) {        // prefetch next tile (overlaps with MMA below)
            long k0 = kbase + (long)(it + 1) * 32;
#pragma unroll
            for (int j = 0; j < 4; j++) {
                int f = t + 256 * j; int row = f >> 3, c4 = f & 7;
                lbuf[j] = *(const float4*)(L + (long)(m0 + row) * N + k0 + c4 * 4);
            }
#pragma unroll
            for (int j = 0; j < 2; j++) {
                int f = t + 256 * j; int row = f >> 4, c4 = f & 15;
                ubuf[j] = *(const float4*)(U + (k0 + row) * 64 + c4 * 4);
            }
        }
#pragma unroll
        for (int kk = 0; kk < 4; kk++) {
            int k = kk * 8;
            unsigned a[2][4], b[4][2];
#pragma unroll
            for (int mi = 0; mi < 2; mi++) {
                int r = warp_m * 32 + mi * 16 + g;
                a[mi][0] = Ls[r][k + tq];
                a[mi][1] = Ls[r + 8][k + tq];
                a[mi][2] = Ls[r][k + tq + 4];
                a[mi][3] = Ls[r + 8][k + tq + 4];
            }
#pragma unroll
            for (int ni = 0; ni < 4; ni++) {
                int c = warp_n * 32 + ni * 8 + g;
                b[ni][0] = Us[k + tq][c];
                b[ni][1] = Us[k + tq + 4][c];
            }
#pragma unroll
            for (int mi = 0; mi < 2; mi++)
#pragma unroll
                for (int ni = 0; ni < 4; ni++)
                    asm volatile(
                        "mma.sync.aligned.m16n8k8.row.col.f32.tf32.tf32.f32 "
                        "{%0,%1,%2,%3}, {%4,%5,%6,%7}, {%8,%9}, {%0,%1,%2,%3};"
                        : "+f"(acc[mi][ni][0]), "+f"(acc[mi][ni][1]),
                          "+f"(acc[mi][ni][2]), "+f"(acc[mi][ni][3])
                        : "r"(a[mi][0]), "r"(a[mi][1]), "r"(a[mi][2]), "r"(a[mi][3]),
                          "r"(b[ni][0]), "r"(b[ni][1]));
        }
        __syncthreads();
    }

    float* Pb = P + (long)blockIdx.y * N * 64;
#pragma unroll
    for (int mi = 0; mi < 2; mi++) {
        int r = m0 + warp_m * 32 + mi * 16 + g;
#pragma unroll
        for (int ni = 0; ni < 4; ni++) {
            int c = warp_n * 32 + ni * 8 + 2 * tq;
            *(float2*)(Pb + (long)r * 64 + c)       = make_float2(acc[mi][ni][0], acc[mi][ni][1]);
            *(float2*)(Pb + (long)(r + 8) * 64 + c) = make_float2(acc[mi][ni][2], acc[mi][ni][3]);
        }
    }
}

// ---------------- combine split-K partials, scale by dinv_i, relu ----------
__global__ void scn_combine_relu(const float4* __restrict__ P, const float* __restrict__ dinv,
                                 float4* __restrict__ X, int N, int S) {
    int idx = blockIdx.x * 256 + threadIdx.x;   // over N*16 float4
    int total4 = N * 16;
    if (idx >= total4) return;
    float4 s = P[idx];
    for (int q = 1; q < S; q++) {
        float4 v = P[(long)q * total4 + idx];
        s.x += v.x; s.y += v.y; s.z += v.z; s.w += v.w;
    }
    float d = dinv[idx >> 4];
    X[idx] = make_float4(fmaxf(d * s.x, 0.f), fmaxf(d * s.y, 0.f),
                         fmaxf(d * s.z, 0.f), fmaxf(d * s.w, 0.f));
}

// ---------------- deterministic segment pooling ----------------
__global__ void scn_pool_partial(const float* __restrict__ X, const int* __restrict__ bel,
                                 float* __restrict__ PP, int N) {
    __shared__ float part[2][BSEG][CCH];
    int t = threadIdx.x;                   // 128 threads
    int c = t & 63, s = t >> 6;
    for (int i = t; i < 2 * BSEG * CCH; i += 128) ((float*)part)[i] = 0.f;
    __syncthreads();
    int r0 = blockIdx.x * 256 + s * 128;
    for (int r = 0; r < 128; r++) {
        int row = r0 + r;
        int b = bel[row];
        part[s][b][c] += X[(long)row * 64 + c];
    }
    __syncthreads();
    float* out = PP + (long)blockIdx.x * BSEG * CCH;
    for (int i = t; i < BSEG * CCH; i += 128)
        out[i] = ((float*)part)[i] + ((float*)part)[BSEG * CCH + i];
}

__global__ void scn_pool_reduce(const float* __restrict__ PP, float* __restrict__ pooled, int G) {
    int idx = blockIdx.x * 256 + threadIdx.x;
    float s = 0.f;
    for (int g = 0; g < G; g++) s += PP[(long)g * BSEG * CCH + idx];
    pooled[idx] = s;
}

// ---------------- readout ----------------
__global__ void scn_readout(const float* __restrict__ pool,
                            const float* __restrict__ Wr0, const float* __restrict__ br0,
                            const float* __restrict__ Wr1, const float* __restrict__ br1,
                            const float* __restrict__ Wr2, const float* __restrict__ br2,
                            float* __restrict__ out) {
    int idx = blockIdx.x * 256 + threadIdx.x;
    if (idx >= BSEG * OUTC) return;
    int b = idx >> 5, o = idx & 31;
    float s = br0[o] + br1[o] + br2[o];
    const float* p0 = pool + 0 * BSEG * CCH + b * 64;
    const float* p1 = pool + 1 * BSEG * CCH + b * 64;
    const float* p2 = pool + 2 * BSEG * CCH + b * 64;
#pragma unroll 8
    for (int c = 0; c < 64; c++) {
        s = fmaf(p0[c], Wr0[c * 32 + o], s);
        s = fmaf(p1[c], Wr1[c * 32 + o], s);
        s = fmaf(p2[c], Wr2[c * 32 + o], s);
    }
    out[idx] = s;
}

// ---------------------------------------------------------------------------
static void* symAddr(const void* sym) {
    void* p = nullptr;
    cudaGetSymbolAddress(&p, sym);
    return p;
}

extern "C" void kernel_launch(void* const* d_in, const int* in_sizes, int n_in,
                              void* d_out, int out_size) {
    const float *x[3], *L[3], *W[3], *Wr[3], *br[3];
    const int* bel[3];

    if (in_sizes[0] == 16777216) {                       // alpha order
        for (int r = 0; r < 3; r++) {
            L[r]  = (const float*)d_in[0 + r];
            W[r]  = (const float*)d_in[3 + r];
            Wr[r] = (const float*)d_in[6 + r];
            bel[r]= (const int*)  d_in[9 + r];
            br[r] = (const float*)d_in[12 + r];
            x[r]  = (const float*)d_in[15 + r];
        }
    } else if (in_sizes[9] == 8192) {                    // dict order
        for (int r = 0; r < 3; r++) {
            x[r]  = (const float*)d_in[0 + r];
            L[r]  = (const float*)d_in[3 + r];
            bel[r]= (const int*)  d_in[6 + r];
            W[r]  = (const float*)d_in[9 + r];
        }
        Wr[0] = (const float*)d_in[12]; br[0] = (const float*)d_in[13];
        Wr[1] = (const float*)d_in[14]; br[1] = (const float*)d_in[15];
        Wr[2] = (const float*)d_in[16]; br[2] = (const float*)d_in[17];
    } else {                                             // signature order
        for (int r = 0; r < 3; r++) {
            x[r]  = (const float*)d_in[0 + r];
            L[r]  = (const float*)d_in[3 + r];
            W[r]  = (const float*)d_in[6 + r];
            bel[r]= (const int*)  d_in[15 + r];
        }
        Wr[0] = (const float*)d_in[9];  br[0] = (const float*)d_in[10];
        Wr[1] = (const float*)d_in[11]; br[1] = (const float*)d_in[12];
        Wr[2] = (const float*)d_in[13]; br[2] = (const float*)d_in[14];
    }

    int Ns[3];
    if (in_sizes[0] == 16777216) {
        Ns[0] = in_sizes[15] / 64; Ns[1] = in_sizes[16] / 64; Ns[2] = in_sizes[17] / 64;
    } else {
        Ns[0] = in_sizes[0] / 64;  Ns[1] = in_sizes[1] / 64;  Ns[2] = in_sizes[2] / 64;
    }

    float* dinvAll = (float*)symAddr(g_dinv);
    float* uAll    = (float*)symAddr(g_u);
    float* xAll    = (float*)symAddr(g_x);
    float* part    = (float*)symAddr(g_part);
    float* pp      = (float*)symAddr(g_pp);
    float* pool    = (float*)symAddr(g_pool);
    float* out     = (float*)d_out;

    // 1) rowsums -> dinv
    for (int r = 0; r < 3; r++)
        scn_rowsum<<<Ns[r], 256>>>(L[r], dinvAll + r * NMAX, Ns[r]);

    // 2) two conv layers per rank (tf32 tensor-core GEMM, split-K one wave)
    for (int r = 0; r < 3; r++) {
        int N = Ns[r];
        int S = (N >= 8192) ? 4 : 8;     // grid = (N/128)*S = 256 CTAs either way
        int kChunk = N / S;              // 2048 / 512 (multiple of 32)
        float* dinv = dinvAll + r * NMAX;
        float* u    = uAll + (long)r * NMAX * CCH;
        float* xr   = xAll + (long)r * NMAX * CCH;
        const float* xin = x[r];
        for (int layer = 0; layer < 2; layer++) {
            scn_xw<<<N / 32, 256>>>(xin, W[r] + layer * 64 * 64, dinv, u, N);
            scn_gemm_tf32<<<dim3(N / 128, S), 256>>>(L[r], u, part, N, kChunk);
            scn_combine_relu<<<N / 16, 256>>>((const float4*)part, dinv, (float4*)xr, N, S);
            xin = xr;
        }
    }

    // 3) deterministic pooling + readout
    for (int r = 0; r < 3; r++) {
        int N = Ns[r];
        int G = N / 256;
        float* xr  = xAll + (long)r * NMAX * CCH;
        float* ppr = pp + (long)r * 32 * BSEG * CCH;
        scn_pool_partial<<<G, 128>>>(xr, bel[r], ppr, N);
        scn_pool_reduce<<<16, 256>>>(ppr, pool + r * BSEG * CCH, G);
    }
    scn_readout<<<8, 256>>>(pool, Wr[0], br[0], Wr[1], br[1], Wr[2], br[2], out);
}

// round 4
// speedup vs baseline: 2.1078x; 1.3027x over previous
#include <cuda_runtime.h>
#include <cuda_bf16.h>

// ---------------------------------------------------------------------------
// SCN: per rank r with L (N x N), x (N x 64), W (2 x 64 x 64):
//   dinv_i = rsqrt(sum_j |L_ij|)  (0 if sum==0)
//   layer:  x = relu( dinv_i * sum_j L_ij * (dinv_j * (x @ W[layer])_j) )
//   pooled[b] = sum_{i: bel_i==b} x_i   (B=64);  out += pooled @ Wr + br
// L @ U on tensor cores (mma.sync tf32 with cvt.rna fragment rounding),
// cp.async double-buffered pipeline, 3 concurrent per-rank streams.
// ---------------------------------------------------------------------------

#define NMAX   8192
#define CCH    64
#define BSEG   64
#define OUTC   32
#define SPLIT_ELEMS 2097152            // S*N*64: 4*8192*64 == 8*4096*64

__device__ float g_dinv[3 * NMAX];
__device__ float g_u[3][NMAX * CCH];
__device__ float g_x[3][NMAX * CCH];
__device__ float g_part[3][SPLIT_ELEMS];     // per-rank split-K scratch
__device__ float g_pp[3 * 32 * BSEG * CCH];
__device__ float g_pool[3 * BSEG * CCH];

// ---------------- rowsum -> dinv ----------------
__global__ void scn_rowsum(const float* __restrict__ L, float* __restrict__ dinv, int N) {
    int row = blockIdx.x;
    const float4* Lr = (const float4*)(L + (long)row * N);
    int n4 = N >> 2;
    float s = 0.f;
    for (int j = threadIdx.x; j < n4; j += blockDim.x) {
        float4 v = Lr[j];
        s += fabsf(v.x) + fabsf(v.y) + fabsf(v.z) + fabsf(v.w);
    }
#pragma unroll
    for (int o = 16; o > 0; o >>= 1) s += __shfl_down_sync(0xffffffffu, s, o);
    __shared__ float red[8];
    int lane = threadIdx.x & 31, w = threadIdx.x >> 5;
    if (lane == 0) red[w] = s;
    __syncthreads();
    if (threadIdx.x < 8) {
        s = red[threadIdx.x];
#pragma unroll
        for (int o = 4; o > 0; o >>= 1) s += __shfl_down_sync(0xffu, s, o);
        if (threadIdx.x == 0) dinv[row] = (s > 0.f) ? rsqrtf(s) : 0.f;
    }
}

// ---------------- u = dinv .* (x @ W)  (N x 64) ----------------
__global__ void scn_xw(const float* __restrict__ X, const float* __restrict__ W,
                       const float* __restrict__ dinv, float* __restrict__ U, int N) {
    __shared__ float Ws[64][64];
    __shared__ float Xs[32][64];
    int t = threadIdx.x;
    int r0 = blockIdx.x * 32;
#pragma unroll
    for (int j = 0; j < 4; j++)
        ((float4*)Ws)[t + 256 * j] = ((const float4*)W)[t + 256 * j];
#pragma unroll
    for (int j = 0; j < 2; j++)
        ((float4*)Xs)[t + 256 * j] = ((const float4*)(X + (long)r0 * 64))[t + 256 * j];
    __syncthreads();
    int c = t & 63, g = t >> 6;
    float acc[8] = {0.f, 0.f, 0.f, 0.f, 0.f, 0.f, 0.f, 0.f};
#pragma unroll 16
    for (int k = 0; k < 64; k++) {
        float w = Ws[k][c];
#pragma unroll
        for (int r = 0; r < 8; r++)
            acc[r] = fmaf(Xs[g * 8 + r][k], w, acc[r]);
    }
#pragma unroll
    for (int r = 0; r < 8; r++) {
        int row = r0 + g * 8 + r;
        U[(long)row * 64 + c] = dinv[row] * acc[r];
    }
}

// ---------------- tf32 tensor-core split-K GEMM, cp.async pipeline ----------
#define LS_STRIDE 36
#define US_STRIDE 68
#define LS_SZ (128 * LS_STRIDE)
#define US_SZ (32 * US_STRIDE)
#define GEMM_SMEM ((2 * (LS_SZ + US_SZ)) * 4)

__device__ __forceinline__ void cpa16(unsigned smaddr, const void* g) {
    asm volatile("cp.async.cg.shared.global [%0], [%1], 16;" :: "r"(smaddr), "l"(g));
}
__device__ __forceinline__ unsigned rna(unsigned x) {
    unsigned r;
    asm("cvt.rna.tf32.f32 %0, %1;" : "=r"(r) : "r"(x));
    return r;
}

__global__ __launch_bounds__(256, 3)
void scn_gemm_tf32(const float* __restrict__ L, const float* __restrict__ U,
                   float* __restrict__ P, int N, int kChunk) {
    extern __shared__ float smem[];
    unsigned sbase = (unsigned)__cvta_generic_to_shared(smem);
    const unsigned* SU = (const unsigned*)smem;
    unsigned ls_addr = sbase;
    unsigned us_addr = sbase + 2u * LS_SZ * 4u;
    const int us_off = 2 * LS_SZ;

    int t = threadIdx.x;
    int wid = t >> 5, lane = t & 31;
    int g = lane >> 2, tq = lane & 3;
    int warp_m = wid & 3, warp_n = wid >> 2;          // 4 x 2 warp grid
    int m0 = blockIdx.x * 128;
    long kbase = (long)blockIdx.y * kChunk;
    int iters = kChunk / 32;

    // precompute cp.async thread slots
    int l_row[4], l_c4[4], u_row[2], u_c4[2];
#pragma unroll
    for (int j = 0; j < 4; j++) { int f = t + 256 * j; l_row[j] = f >> 3; l_c4[j] = f & 7; }
#pragma unroll
    for (int j = 0; j < 2; j++) { int f = t + 256 * j; u_row[j] = f >> 4; u_c4[j] = f & 15; }

    float acc[2][4][4];
#pragma unroll
    for (int mi = 0; mi < 2; mi++)
#pragma unroll
        for (int ni = 0; ni < 4; ni++)
#pragma unroll
            for (int q = 0; q < 4; q++) acc[mi][ni][q] = 0.f;

#define ISSUE_TILE(IT, BUF)                                                              \
    do {                                                                                 \
        long k0_ = kbase + (long)(IT) * 32;                                              \
        _Pragma("unroll")                                                                \
        for (int j = 0; j < 4; j++)                                                      \
            cpa16(ls_addr + ((BUF) * LS_SZ + l_row[j] * LS_STRIDE + l_c4[j] * 4) * 4u,   \
                  L + (long)(m0 + l_row[j]) * N + k0_ + l_c4[j] * 4);                    \
        _Pragma("unroll")                                                                \
        for (int j = 0; j < 2; j++)                                                      \
            cpa16(us_addr + ((BUF) * US_SZ + u_row[j] * US_STRIDE + u_c4[j] * 4) * 4u,   \
                  U + (k0_ + u_row[j]) * 64 + u_c4[j] * 4);                              \
        asm volatile("cp.async.commit_group;");                                          \
    } while (0)

    ISSUE_TILE(0, 0);

    for (int it = 0; it < iters; it++) {
        int buf = it & 1;
        if (it + 1 < iters) {
            ISSUE_TILE(it + 1, buf ^ 1);
            asm volatile("cp.async.wait_group 1;");
        } else {
            asm volatile("cp.async.wait_group 0;");
        }
        __syncthreads();

        const unsigned* Lb = SU + buf * LS_SZ;
        const unsigned* Ub = SU + us_off + buf * US_SZ;
#pragma unroll
        for (int kk = 0; kk < 4; kk++) {
            int k = kk * 8;
            unsigned a[2][4], b[4][2];
#pragma unroll
            for (int mi = 0; mi < 2; mi++) {
                int r = warp_m * 32 + mi * 16 + g;
                a[mi][0] = rna(Lb[r * LS_STRIDE + k + tq]);
                a[mi][1] = rna(Lb[(r + 8) * LS_STRIDE + k + tq]);
                a[mi][2] = rna(Lb[r * LS_STRIDE + k + tq + 4]);
                a[mi][3] = rna(Lb[(r + 8) * LS_STRIDE + k + tq + 4]);
            }
#pragma unroll
            for (int ni = 0; ni < 4; ni++) {
                int c = warp_n * 32 + ni * 8 + g;
                b[ni][0] = rna(Ub[(k + tq) * US_STRIDE + c]);
                b[ni][1] = rna(Ub[(k + tq + 4) * US_STRIDE + c]);
            }
#pragma unroll
            for (int mi = 0; mi < 2; mi++)
#pragma unroll
                for (int ni = 0; ni < 4; ni++)
                    asm volatile(
                        "mma.sync.aligned.m16n8k8.row.col.f32.tf32.tf32.f32 "
                        "{%0,%1,%2,%3}, {%4,%5,%6,%7}, {%8,%9}, {%0,%1,%2,%3};"
                        : "+f"(acc[mi][ni][0]), "+f"(acc[mi][ni][1]),
                          "+f"(acc[mi][ni][2]), "+f"(acc[mi][ni][3])
                        : "r"(a[mi][0]), "r"(a[mi][1]), "r"(a[mi][2]), "r"(a[mi][3]),
                          "r"(b[ni][0]), "r"(b[ni][1]));
        }
        __syncthreads();
    }

    float* Pb = P + (long)blockIdx.y * N * 64;
#pragma unroll
    for (int mi = 0; mi < 2; mi++) {
        int r = m0 + warp_m * 32 + mi * 16 + g;
#pragma unroll
        for (int ni = 0; ni < 4; ni++) {
            int c = warp_n * 32 + ni * 8 + 2 * tq;
            *(float2*)(Pb + (long)r * 64 + c)       = make_float2(acc[mi][ni][0], acc[mi][ni][1]);
            *(float2*)(Pb + (long)(r + 8) * 64 + c) = make_float2(acc[mi][ni][2], acc[mi][ni][3]);
        }
    }
}

// ---------------- combine split-K partials, scale by dinv_i, relu ----------
__global__ void scn_combine_relu(const float4* __restrict__ P, const float* __restrict__ dinv,
                                 float4* __restrict__ X, int N, int S) {
    int idx = blockIdx.x * 256 + threadIdx.x;   // over N*16 float4
    int total4 = N * 16;
    if (idx >= total4) return;
    float4 s = P[idx];
    for (int q = 1; q < S; q++) {
        float4 v = P[(long)q * total4 + idx];
        s.x += v.x; s.y += v.y; s.z += v.z; s.w += v.w;
    }
    float d = dinv[idx >> 4];
    X[idx] = make_float4(fmaxf(d * s.x, 0.f), fmaxf(d * s.y, 0.f),
                         fmaxf(d * s.z, 0.f), fmaxf(d * s.w, 0.f));
}

// ---------------- deterministic segment pooling ----------------
__global__ void scn_pool_partial(const float* __restrict__ X, const int* __restrict__ bel,
                                 float* __restrict__ PP, int N) {
    __shared__ float part[2][BSEG][CCH];
    int t = threadIdx.x;                   // 128 threads
    int c = t & 63, s = t >> 6;
    for (int i = t; i < 2 * BSEG * CCH; i += 128) ((float*)part)[i] = 0.f;
    __syncthreads();
    int r0 = blockIdx.x * 256 + s * 128;
    for (int r = 0; r < 128; r++) {
        int row = r0 + r;
        int b = bel[row];
        part[s][b][c] += X[(long)row * 64 + c];
    }
    __syncthreads();
    float* out = PP + (long)blockIdx.x * BSEG * CCH;
    for (int i = t; i < BSEG * CCH; i += 128)
        out[i] = ((float*)part)[i] + ((float*)part)[BSEG * CCH + i];
}

__global__ void scn_pool_reduce(const float* __restrict__ PP, float* __restrict__ pooled, int G) {
    int idx = blockIdx.x * 256 + threadIdx.x;
    float s = 0.f;
    for (int g = 0; g < G; g++) s += PP[(long)g * BSEG * CCH + idx];
    pooled[idx] = s;
}

// ---------------- readout ----------------
__global__ void scn_readout(const float* __restrict__ pool,
                            const float* __restrict__ Wr0, const float* __restrict__ br0,
                            const float* __restrict__ Wr1, const float* __restrict__ br1,
                            const float* __restrict__ Wr2, const float* __restrict__ br2,
                            float* __restrict__ out) {
    int idx = blockIdx.x * 256 + threadIdx.x;
    if (idx >= BSEG * OUTC) return;
    int b = idx >> 5, o = idx & 31;
    float s = br0[o] + br1[o] + br2[o];
    const float* p0 = pool + 0 * BSEG * CCH + b * 64;
    const float* p1 = pool + 1 * BSEG * CCH + b * 64;
    const float* p2 = pool + 2 * BSEG * CCH + b * 64;
#pragma unroll 8
    for (int c = 0; c < 64; c++) {
        s = fmaf(p0[c], Wr0[c * 32 + o], s);
        s = fmaf(p1[c], Wr1[c * 32 + o], s);
        s = fmaf(p2[c], Wr2[c * 32 + o], s);
    }
    out[idx] = s;
}

// ---------------------------------------------------------------------------
static void* symAddr(const void* sym) {
    void* p = nullptr;
    cudaGetSymbolAddress(&p, sym);
    return p;
}

extern "C" void kernel_launch(void* const* d_in, const int* in_sizes, int n_in,
                              void* d_out, int out_size) {
    const float *x[3], *L[3], *W[3], *Wr[3], *br[3];
    const int* bel[3];

    if (in_sizes[0] == 16777216) {                       // alpha order
        for (int r = 0; r < 3; r++) {
            L[r]  = (const float*)d_in[0 + r];
            W[r]  = (const float*)d_in[3 + r];
            Wr[r] = (const float*)d_in[6 + r];
            bel[r]= (const int*)  d_in[9 + r];
            br[r] = (const float*)d_in[12 + r];
            x[r]  = (const float*)d_in[15 + r];
        }
    } else if (in_sizes[9] == 8192) {                    // dict order
        for (int r = 0; r < 3; r++) {
            x[r]  = (const float*)d_in[0 + r];
            L[r]  = (const float*)d_in[3 + r];
            bel[r]= (const int*)  d_in[6 + r];
            W[r]  = (const float*)d_in[9 + r];
        }
        Wr[0] = (const float*)d_in[12]; br[0] = (const float*)d_in[13];
        Wr[1] = (const float*)d_in[14]; br[1] = (const float*)d_in[15];
        Wr[2] = (const float*)d_in[16]; br[2] = (const float*)d_in[17];
    } else {                                             // signature order
        for (int r = 0; r < 3; r++) {
            x[r]  = (const float*)d_in[0 + r];
            L[r]  = (const float*)d_in[3 + r];
            W[r]  = (const float*)d_in[6 + r];
            bel[r]= (const int*)  d_in[15 + r];
        }
        Wr[0] = (const float*)d_in[9];  br[0] = (const float*)d_in[10];
        Wr[1] = (const float*)d_in[11]; br[1] = (const float*)d_in[12];
        Wr[2] = (const float*)d_in[13]; br[2] = (const float*)d_in[14];
    }

    int Ns[3];
    if (in_sizes[0] == 16777216) {
        Ns[0] = in_sizes[15] / 64; Ns[1] = in_sizes[16] / 64; Ns[2] = in_sizes[17] / 64;
    } else {
        Ns[0] = in_sizes[0] / 64;  Ns[1] = in_sizes[1] / 64;  Ns[2] = in_sizes[2] / 64;
    }

    float* dinvAll = (float*)symAddr(g_dinv);
    float* uAll    = (float*)symAddr(g_u);
    float* xAll    = (float*)symAddr(g_x);
    float* part    = (float*)symAddr(g_part);
    float* pp      = (float*)symAddr(g_pp);
    float* pool    = (float*)symAddr(g_pool);
    float* out     = (float*)d_out;

    cudaFuncSetAttribute(scn_gemm_tf32, cudaFuncAttributeMaxDynamicSharedMemorySize, GEMM_SMEM);

    // Fork three per-rank streams off the capture stream (stream 0).
    cudaStream_t st[3];
    cudaEvent_t root, ev[3];
    cudaEventCreateWithFlags(&root, cudaEventDisableTiming);
    cudaEventRecord(root, 0);
    for (int r = 0; r < 3; r++) {
        cudaStreamCreateWithFlags(&st[r], cudaStreamNonBlocking);
        cudaEventCreateWithFlags(&ev[r], cudaEventDisableTiming);
        cudaStreamWaitEvent(st[r], root, 0);
    }

    for (int r = 0; r < 3; r++) {
        int N = Ns[r];
        int S = (N >= 8192) ? 4 : 8;     // grid = (N/128)*S = 256 CTAs per GEMM
        int kChunk = N / S;
        float* dinv = dinvAll + r * NMAX;
        float* u    = uAll + (long)r * NMAX * CCH;
        float* xr   = xAll + (long)r * NMAX * CCH;
        float* pr   = part + (long)r * SPLIT_ELEMS;
        const float* xin = x[r];

        scn_rowsum<<<N, 256, 0, st[r]>>>(L[r], dinv, N);
        for (int layer = 0; layer < 2; layer++) {
            scn_xw<<<N / 32, 256, 0, st[r]>>>(xin, W[r] + layer * 64 * 64, dinv, u, N);
            scn_gemm_tf32<<<dim3(N / 128, S), 256, GEMM_SMEM, st[r]>>>(L[r], u, pr, N, kChunk);
            scn_combine_relu<<<N / 16, 256, 0, st[r]>>>((const float4*)pr, dinv, (float4*)xr, N, S);
            xin = xr;
        }
        int G = N / 256;
        float* ppr = pp + (long)r * 32 * BSEG * CCH;
        scn_pool_partial<<<G, 128, 0, st[r]>>>(xr, bel[r], ppr, N);
        scn_pool_reduce<<<16, 256, 0, st[r]>>>(ppr, pool + r * BSEG * CCH, G);
        cudaEventRecord(ev[r], st[r]);
    }

    // Join back to the capture stream and run the readout there.
    for (int r = 0; r < 3; r++) cudaStreamWaitEvent((cudaStream_t)0, ev[r], 0);
    scn_readout<<<8, 256>>>(pool, Wr[0], br[0], Wr[1], br[1], Wr[2], br[2], out);

    for (int r = 0; r < 3; r++) {
        cudaStreamDestroy(st[r]);
        cudaEventDestroy(ev[r]);
    }
    cudaEventDestroy(root);
}

// round 6
// speedup vs baseline: 2.3586x; 1.1190x over previous
#include <cuda_runtime.h>
#include <cuda_bf16.h>

// ---------------------------------------------------------------------------
// SCN: per rank r with L (N x N), x (N x 64), W (2 x 64 x 64):
//   dinv_i = rsqrt(sum_j |L_ij|)  (0 if sum==0)
//   layer:  x = relu( dinv_i * sum_j L_ij * (dinv_j * (x @ W[layer])_j) )
//   pooled[b] = sum_{i: bel_i==b} x_i   (B=64);  out += pooled @ Wr + br
// L @ U on tensor cores (mma.sync tf32, cvt.rna fragment rounding),
// BK=64 cp.async double-buffered pipeline, fused combine+xw, 3 streams.
// ---------------------------------------------------------------------------

#define NMAX   8192
#define CCH    64
#define BSEG   64
#define OUTC   32
#define SPLIT_ELEMS 2097152            // S*N*64: 4*8192*64 == 8*4096*64

__device__ float g_dinv[3 * NMAX];
__device__ float g_u[3][NMAX * CCH];
__device__ float g_x[3][NMAX * CCH];
__device__ float g_part[3][SPLIT_ELEMS];     // per-rank split-K scratch
__device__ float g_pp[3 * 32 * BSEG * CCH];
__device__ float g_pool[3 * BSEG * CCH];

// ---------------- rowsum -> dinv ----------------
__global__ void scn_rowsum(const float* __restrict__ L, float* __restrict__ dinv, int N) {
    int row = blockIdx.x;
    const float4* Lr = (const float4*)(L + (long)row * N);
    int n4 = N >> 2;
    float s = 0.f;
    for (int j = threadIdx.x; j < n4; j += blockDim.x) {
        float4 v = Lr[j];
        s += fabsf(v.x) + fabsf(v.y) + fabsf(v.z) + fabsf(v.w);
    }
#pragma unroll
    for (int o = 16; o > 0; o >>= 1) s += __shfl_down_sync(0xffffffffu, s, o);
    __shared__ float red[8];
    int lane = threadIdx.x & 31, w = threadIdx.x >> 5;
    if (lane == 0) red[w] = s;
    __syncthreads();
    if (threadIdx.x < 8) {
        s = red[threadIdx.x];
#pragma unroll
        for (int o = 4; o > 0; o >>= 1) s += __shfl_down_sync(0xffu, s, o);
        if (threadIdx.x == 0) dinv[row] = (s > 0.f) ? rsqrtf(s) : 0.f;
    }
}

// ---------------- u = dinv .* (x @ W)  (first layer, x from input) ---------
__global__ void scn_xw(const float* __restrict__ X, const float* __restrict__ W,
                       const float* __restrict__ dinv, float* __restrict__ U, int N) {
    __shared__ float Ws[64][64];
    __shared__ float Xs[32][64];
    int t = threadIdx.x;
    int r0 = blockIdx.x * 32;
#pragma unroll
    for (int j = 0; j < 4; j++)
        ((float4*)Ws)[t + 256 * j] = ((const float4*)W)[t + 256 * j];
#pragma unroll
    for (int j = 0; j < 2; j++)
        ((float4*)Xs)[t + 256 * j] = ((const float4*)(X + (long)r0 * 64))[t + 256 * j];
    __syncthreads();
    int c = t & 63, g = t >> 6;
    float acc[8] = {0.f, 0.f, 0.f, 0.f, 0.f, 0.f, 0.f, 0.f};
#pragma unroll 16
    for (int k = 0; k < 64; k++) {
        float w = Ws[k][c];
#pragma unroll
        for (int r = 0; r < 8; r++)
            acc[r] = fmaf(Xs[g * 8 + r][k], w, acc[r]);
    }
#pragma unroll
    for (int r = 0; r < 8; r++) {
        int row = r0 + g * 8 + r;
        U[(long)row * 64 + c] = dinv[row] * acc[r];
    }
}

// ---------------- tf32 tensor-core split-K GEMM, BK=64 cp.async ------------
#define LS_STRIDE 68
#define US_STRIDE 68
#define LS_SZ (128 * LS_STRIDE)
#define US_SZ (64 * US_STRIDE)
#define GEMM_SMEM ((2 * (LS_SZ + US_SZ)) * 4)

__device__ __forceinline__ void cpa16(unsigned smaddr, const void* g) {
    asm volatile("cp.async.cg.shared.global [%0], [%1], 16;" :: "r"(smaddr), "l"(g));
}
__device__ __forceinline__ unsigned rna(unsigned x) {
    unsigned r;
    asm("cvt.rna.tf32.f32 %0, %1;" : "=r"(r) : "r"(x));
    return r;
}

__global__ __launch_bounds__(256, 2)
void scn_gemm_tf32(const float* __restrict__ L, const float* __restrict__ U,
                   float* __restrict__ P, int N, int kChunk) {
    extern __shared__ float smem[];
    unsigned sbase = (unsigned)__cvta_generic_to_shared(smem);
    const unsigned* SU = (const unsigned*)smem;
    unsigned ls_addr = sbase;
    unsigned us_addr = sbase + 2u * LS_SZ * 4u;
    const int us_off = 2 * LS_SZ;

    int t = threadIdx.x;
    int wid = t >> 5, lane = t & 31;
    int g = lane >> 2, tq = lane & 3;
    int warp_m = wid & 3, warp_n = wid >> 2;          // 4 x 2 warp grid
    int m0 = blockIdx.x * 128;
    long kbase = (long)blockIdx.y * kChunk;
    int iters = kChunk / 64;

    // cp.async thread slots: L 128x64 (2048 float4), U 64x64 (1024 float4)
    int l_row[8], l_c4[8], u_row[4], u_c4[4];
#pragma unroll
    for (int j = 0; j < 8; j++) { int f = t + 256 * j; l_row[j] = f >> 4; l_c4[j] = f & 15; }
#pragma unroll
    for (int j = 0; j < 4; j++) { int f = t + 256 * j; u_row[j] = f >> 4; u_c4[j] = f & 15; }

    float acc[2][4][4];
#pragma unroll
    for (int mi = 0; mi < 2; mi++)
#pragma unroll
        for (int ni = 0; ni < 4; ni++)
#pragma unroll
            for (int q = 0; q < 4; q++) acc[mi][ni][q] = 0.f;

#define ISSUE_TILE(IT, BUF)                                                              \
    do {                                                                                 \
        long k0_ = kbase + (long)(IT) * 64;                                              \
        _Pragma("unroll")                                                                \
        for (int j = 0; j < 8; j++)                                                      \
            cpa16(ls_addr + ((BUF) * LS_SZ + l_row[j] * LS_STRIDE + l_c4[j] * 4) * 4u,   \
                  L + (long)(m0 + l_row[j]) * N + k0_ + l_c4[j] * 4);                    \
        _Pragma("unroll")                                                                \
        for (int j = 0; j < 4; j++)                                                      \
            cpa16(us_addr + ((BUF) * US_SZ + u_row[j] * US_STRIDE + u_c4[j] * 4) * 4u,   \
                  U + (k0_ + u_row[j]) * 64 + u_c4[j] * 4);                              \
        asm volatile("cp.async.commit_group;");                                          \
    } while (0)

    ISSUE_TILE(0, 0);

    for (int it = 0; it < iters; it++) {
        int buf = it & 1;
        if (it + 1 < iters) {
            ISSUE_TILE(it + 1, buf ^ 1);
            asm volatile("cp.async.wait_group 1;");
        } else {
            asm volatile("cp.async.wait_group 0;");
        }
        __syncthreads();

        const unsigned* Lb = SU + buf * LS_SZ;
        const unsigned* Ub = SU + us_off + buf * US_SZ;
#pragma unroll
        for (int kk = 0; kk < 8; kk++) {
            int k = kk * 8;
            unsigned a[2][4], b[4][2];
#pragma unroll
            for (int mi = 0; mi < 2; mi++) {
                int r = warp_m * 32 + mi * 16 + g;
                a[mi][0] = rna(Lb[r * LS_STRIDE + k + tq]);
                a[mi][1] = rna(Lb[(r + 8) * LS_STRIDE + k + tq]);
                a[mi][2] = rna(Lb[r * LS_STRIDE + k + tq + 4]);
                a[mi][3] = rna(Lb[(r + 8) * LS_STRIDE + k + tq + 4]);
            }
#pragma unroll
            for (int ni = 0; ni < 4; ni++) {
                int c = warp_n * 32 + ni * 8 + g;
                b[ni][0] = rna(Ub[(k + tq) * US_STRIDE + c]);
                b[ni][1] = rna(Ub[(k + tq + 4) * US_STRIDE + c]);
            }
#pragma unroll
            for (int mi = 0; mi < 2; mi++)
#pragma unroll
                for (int ni = 0; ni < 4; ni++)
                    asm volatile(
                        "mma.sync.aligned.m16n8k8.row.col.f32.tf32.tf32.f32 "
                        "{%0,%1,%2,%3}, {%4,%5,%6,%7}, {%8,%9}, {%0,%1,%2,%3};"
                        : "+f"(acc[mi][ni][0]), "+f"(acc[mi][ni][1]),
                          "+f"(acc[mi][ni][2]), "+f"(acc[mi][ni][3])
                        : "r"(a[mi][0]), "r"(a[mi][1]), "r"(a[mi][2]), "r"(a[mi][3]),
                          "r"(b[ni][0]), "r"(b[ni][1]));
        }
        __syncthreads();
    }

    float* Pb = P + (long)blockIdx.y * N * 64;
#pragma unroll
    for (int mi = 0; mi < 2; mi++) {
        int r = m0 + warp_m * 32 + mi * 16 + g;
#pragma unroll
        for (int ni = 0; ni < 4; ni++) {
            int c = warp_n * 32 + ni * 8 + 2 * tq;
            *(float2*)(Pb + (long)r * 64 + c)       = make_float2(acc[mi][ni][0], acc[mi][ni][1]);
            *(float2*)(Pb + (long)(r + 8) * 64 + c) = make_float2(acc[mi][ni][2], acc[mi][ni][3]);
        }
    }
}

// ---------------- fused: combine split-K + relu + next-layer xW -> U -------
__global__ __launch_bounds__(256)
void scn_combine_xw(const float* __restrict__ P, const float* __restrict__ dinv,
                    const float* __restrict__ W, float* __restrict__ U, int N, int S) {
    __shared__ float Ws[64][64];
    __shared__ float Xs[32][64];
    int t = threadIdx.x;
    int r0 = blockIdx.x * 32;
#pragma unroll
    for (int j = 0; j < 4; j++)
        ((float4*)Ws)[t + 256 * j] = ((const float4*)W)[t + 256 * j];

    // combine: 32x64 tile = 512 float4, two per thread (FIX: full coverage)
    long stride4 = (long)N * 16;
#pragma unroll
    for (int j = 0; j < 2; j++) {
        int f = t + 256 * j;
        int lrow = f >> 4, c4 = f & 15;
        long base = (long)(r0 + lrow) * 16 + c4;
        float4 s = ((const float4*)P)[base];
        for (int q = 1; q < S; q++) {
            float4 v = ((const float4*)P)[(long)q * stride4 + base];
            s.x += v.x; s.y += v.y; s.z += v.z; s.w += v.w;
        }
        float d = dinv[r0 + lrow];
        *(float4*)&Xs[lrow][c4 * 4] = make_float4(
            fmaxf(d * s.x, 0.f), fmaxf(d * s.y, 0.f),
            fmaxf(d * s.z, 0.f), fmaxf(d * s.w, 0.f));
    }
    __syncthreads();

    int c = t & 63, g = t >> 6;
    float acc[8] = {0.f, 0.f, 0.f, 0.f, 0.f, 0.f, 0.f, 0.f};
#pragma unroll 16
    for (int k = 0; k < 64; k++) {
        float w = Ws[k][c];
#pragma unroll
        for (int r = 0; r < 8; r++)
            acc[r] = fmaf(Xs[g * 8 + r][k], w, acc[r]);
    }
#pragma unroll
    for (int r = 0; r < 8; r++) {
        int row = r0 + g * 8 + r;
        U[(long)row * 64 + c] = dinv[row] * acc[r];
    }
}

// ---------------- final combine (writes x for pooling) ----------------
__global__ void scn_combine_relu(const float4* __restrict__ P, const float* __restrict__ dinv,
                                 float4* __restrict__ X, int N, int S) {
    int idx = blockIdx.x * 256 + threadIdx.x;   // over N*16 float4
    int total4 = N * 16;
    if (idx >= total4) return;
    float4 s = P[idx];
    for (int q = 1; q < S; q++) {
        float4 v = P[(long)q * total4 + idx];
        s.x += v.x; s.y += v.y; s.z += v.z; s.w += v.w;
    }
    float d = dinv[idx >> 4];
    X[idx] = make_float4(fmaxf(d * s.x, 0.f), fmaxf(d * s.y, 0.f),
                         fmaxf(d * s.z, 0.f), fmaxf(d * s.w, 0.f));
}

// ---------------- deterministic segment pooling ----------------
__global__ void scn_pool_partial(const float* __restrict__ X, const int* __restrict__ bel,
                                 float* __restrict__ PP, int N) {
    __shared__ float part[2][BSEG][CCH];
    int t = threadIdx.x;                   // 128 threads
    int c = t & 63, s = t >> 6;
    for (int i = t; i < 2 * BSEG * CCH; i += 128) ((float*)part)[i] = 0.f;
    __syncthreads();
    int r0 = blockIdx.x * 256 + s * 128;
    for (int r = 0; r < 128; r++) {
        int row = r0 + r;
        int b = bel[row];
        part[s][b][c] += X[(long)row * 64 + c];
    }
    __syncthreads();
    float* out = PP + (long)blockIdx.x * BSEG * CCH;
    for (int i = t; i < BSEG * CCH; i += 128)
        out[i] = ((float*)part)[i] + ((float*)part)[BSEG * CCH + i];
}

__global__ void scn_pool_reduce(const float* __restrict__ PP, float* __restrict__ pooled, int G) {
    int idx = blockIdx.x * 256 + threadIdx.x;
    float s = 0.f;
    for (int g = 0; g < G; g++) s += PP[(long)g * BSEG * CCH + idx];
    pooled[idx] = s;
}

// ---------------- readout ----------------
__global__ void scn_readout(const float* __restrict__ pool,
                            const float* __restrict__ Wr0, const float* __restrict__ br0,
                            const float* __restrict__ Wr1, const float* __restrict__ br1,
                            const float* __restrict__ Wr2, const float* __restrict__ br2,
                            float* __restrict__ out) {
    int idx = blockIdx.x * 256 + threadIdx.x;
    if (idx >= BSEG * OUTC) return;
    int b = idx >> 5, o = idx & 31;
    float s = br0[o] + br1[o] + br2[o];
    const float* p0 = pool + 0 * BSEG * CCH + b * 64;
    const float* p1 = pool + 1 * BSEG * CCH + b * 64;
    const float* p2 = pool + 2 * BSEG * CCH + b * 64;
#pragma unroll 8
    for (int c = 0; c < 64; c++) {
        s = fmaf(p0[c], Wr0[c * 32 + o], s);
        s = fmaf(p1[c], Wr1[c * 32 + o], s);
        s = fmaf(p2[c], Wr2[c * 32 + o], s);
    }
    out[idx] = s;
}

// ---------------------------------------------------------------------------
static void* symAddr(const void* sym) {
    void* p = nullptr;
    cudaGetSymbolAddress(&p, sym);
    return p;
}

extern "C" void kernel_launch(void* const* d_in, const int* in_sizes, int n_in,
                              void* d_out, int out_size) {
    const float *x[3], *L[3], *W[3], *Wr[3], *br[3];
    const int* bel[3];

    if (in_sizes[0] == 16777216) {                       // alpha order
        for (int r = 0; r < 3; r++) {
            L[r]  = (const float*)d_in[0 + r];
            W[r]  = (const float*)d_in[3 + r];
            Wr[r] = (const float*)d_in[6 + r];
            bel[r]= (const int*)  d_in[9 + r];
            br[r] = (const float*)d_in[12 + r];
            x[r]  = (const float*)d_in[15 + r];
        }
    } else if (in_sizes[9] == 8192) {                    // dict order
        for (int r = 0; r < 3; r++) {
            x[r]  = (const float*)d_in[0 + r];
            L[r]  = (const float*)d_in[3 + r];
            bel[r]= (const int*)  d_in[6 + r];
            W[r]  = (const float*)d_in[9 + r];
        }
        Wr[0] = (const float*)d_in[12]; br[0] = (const float*)d_in[13];
        Wr[1] = (const float*)d_in[14]; br[1] = (const float*)d_in[15];
        Wr[2] = (const float*)d_in[16]; br[2] = (const float*)d_in[17];
    } else {                                             // signature order
        for (int r = 0; r < 3; r++) {
            x[r]  = (const float*)d_in[0 + r];
            L[r]  = (const float*)d_in[3 + r];
            W[r]  = (const float*)d_in[6 + r];
            bel[r]= (const int*)  d_in[15 + r];
        }
        Wr[0] = (const float*)d_in[9];  br[0] = (const float*)d_in[10];
        Wr[1] = (const float*)d_in[11]; br[1] = (const float*)d_in[12];
        Wr[2] = (const float*)d_in[13]; br[2] = (const float*)d_in[14];
    }

    int Ns[3];
    if (in_sizes[0] == 16777216) {
        Ns[0] = in_sizes[15] / 64; Ns[1] = in_sizes[16] / 64; Ns[2] = in_sizes[17] / 64;
    } else {
        Ns[0] = in_sizes[0] / 64;  Ns[1] = in_sizes[1] / 64;  Ns[2] = in_sizes[2] / 64;
    }

    float* dinvAll = (float*)symAddr(g_dinv);
    float* uAll    = (float*)symAddr(g_u);
    float* xAll    = (float*)symAddr(g_x);
    float* part    = (float*)symAddr(g_part);
    float* pp      = (float*)symAddr(g_pp);
    float* pool    = (float*)symAddr(g_pool);
    float* out     = (float*)d_out;

    cudaFuncSetAttribute(scn_gemm_tf32, cudaFuncAttributeMaxDynamicSharedMemorySize, GEMM_SMEM);

    // Fork three per-rank streams off the capture stream (stream 0).
    cudaStream_t st[3];
    cudaEvent_t root, ev[3];
    cudaEventCreateWithFlags(&root, cudaEventDisableTiming);
    cudaEventRecord(root, 0);
    for (int r = 0; r < 3; r++) {
        cudaStreamCreateWithFlags(&st[r], cudaStreamNonBlocking);
        cudaEventCreateWithFlags(&ev[r], cudaEventDisableTiming);
        cudaStreamWaitEvent(st[r], root, 0);
    }

    for (int r = 0; r < 3; r++) {
        int N = Ns[r];
        int S = (N >= 8192) ? 4 : 8;     // grid = (N/128)*S = 256 CTAs per GEMM
        int kChunk = N / S;
        float* dinv = dinvAll + r * NMAX;
        float* u    = uAll + (long)r * NMAX * CCH;
        float* xr   = xAll + (long)r * NMAX * CCH;
        float* pr   = part + (long)r * SPLIT_ELEMS;

        scn_rowsum<<<N, 256, 0, st[r]>>>(L[r], dinv, N);
        // layer 0
        scn_xw<<<N / 32, 256, 0, st[r]>>>(x[r], W[r], dinv, u, N);
        scn_gemm_tf32<<<dim3(N / 128, S), 256, GEMM_SMEM, st[r]>>>(L[r], u, pr, N, kChunk);
        // combine + relu + layer-1 xW fused
        scn_combine_xw<<<N / 32, 256, 0, st[r]>>>(pr, dinv, W[r] + 64 * 64, u, N, S);
        // layer 1
        scn_gemm_tf32<<<dim3(N / 128, S), 256, GEMM_SMEM, st[r]>>>(L[r], u, pr, N, kChunk);
        scn_combine_relu<<<N / 16, 256, 0, st[r]>>>((const float4*)pr, dinv, (float4*)xr, N, S);
        // pooling
        int G = N / 256;
        float* ppr = pp + (long)r * 32 * BSEG * CCH;
        scn_pool_partial<<<G, 128, 0, st[r]>>>(xr, bel[r], ppr, N);
        scn_pool_reduce<<<16, 256, 0, st[r]>>>(ppr, pool + r * BSEG * CCH, G);
        cudaEventRecord(ev[r], st[r]);
    }

    // Join back to the capture stream and run the readout there.
    for (int r = 0; r < 3; r++) cudaStreamWaitEvent((cudaStream_t)0, ev[r], 0);
    scn_readout<<<8, 256>>>(pool, Wr[0], br[0], Wr[1], br[1], Wr[2], br[2], out);

    for (int r = 0; r < 3; r++) {
        cudaStreamDestroy(st[r]);
        cudaEventDestroy(ev[r]);
    }
    cudaEventDestroy(root);
}